// round 4
// baseline (speedup 1.0000x reference)
#include <cuda_runtime.h>

#define EMB 1024
#define DKH 64
#define NB 4
#define SL 4096
#define MTOT (NB*SL)

// ---------------- scratch (no allocations allowed) ----------------
__device__ float g_Q[MTOT*DKH];
__device__ float g_K[MTOT*DKH];
__device__ float g_V[MTOT*DKH];

// ---------------- helpers ----------------
__device__ __forceinline__ unsigned f2tf(float f){
    unsigned u; asm("cvt.rna.tf32.f32 %0, %1;" : "=r"(u) : "f"(f)); return u;
}
__device__ __forceinline__ void mma8(float* c,
        unsigned a0, unsigned a1, unsigned a2, unsigned a3,
        unsigned b0, unsigned b1){
    asm volatile(
        "mma.sync.aligned.m16n8k8.row.col.f32.tf32.tf32.f32 "
        "{%0,%1,%2,%3},{%4,%5,%6,%7},{%8,%9},{%0,%1,%2,%3};"
        : "+f"(c[0]), "+f"(c[1]), "+f"(c[2]), "+f"(c[3])
        : "r"(a0), "r"(a1), "r"(a2), "r"(a3), "r"(b0), "r"(b1));
}

// ============================================================================
// Kernel 1: QKV projection.  blockIdx.y: 0 -> Q (from input2, scaled 1/8),
//                                        1 -> K (from input1), 2 -> V (from input1)
// Block tile: 128 rows x 64 cols, K chunked at 32. tf32 stored in smem.
// ============================================================================
__global__ __launch_bounds__(256) void proj_kernel(
    const float* __restrict__ in1, const float* __restrict__ in2,
    const float* __restrict__ Wq, const float* __restrict__ bq,
    const float* __restrict__ Wk, const float* __restrict__ bk,
    const float* __restrict__ Wv, const float* __restrict__ bv)
{
    __shared__ unsigned As[128*36];   // pad 36: A-frag lds conflict-free
    __shared__ unsigned Bs[32*72];    // pad 72: B-frag lds conflict-free

    const int tid = threadIdx.x;
    const int lane = tid & 31;
    const int wid  = tid >> 5;
    const int g  = lane >> 2;    // group id (row within mma tile)
    const int tg = lane & 3;     // thread-in-group (col within mma tile)
    const int wm = wid & 3;      // warp row  (4 warps over M=128 -> 32 rows each)
    const int wn = wid >> 2;     // warp col  (2 warps over N=64  -> 32 cols each)

    const int sel = blockIdx.y;
    const float* A    = (sel == 0) ? in2 : in1;
    const float* W    = (sel == 0) ? Wq : (sel == 1 ? Wk : Wv);
    const float* bias = (sel == 0) ? bq : (sel == 1 ? bk : bv);
    float* out = (sel == 0) ? g_Q : (sel == 1 ? g_K : g_V);
    const float scale = (sel == 0) ? 0.125f : 1.0f;   // fold 1/sqrt(64) into Q

    const int row0 = blockIdx.x * 128;

    float acc[2][4][4];
    #pragma unroll
    for (int i = 0; i < 2; i++)
        #pragma unroll
        for (int j = 0; j < 4; j++)
            #pragma unroll
            for (int e = 0; e < 4; e++) acc[i][j][e] = 0.f;

    for (int kc = 0; kc < EMB; kc += 32) {
        // A tile: 128 x 32 floats, tf32 converted at store
        #pragma unroll
        for (int i = 0; i < 4; i++) {
            int idx = tid + i * 256;          // 0..1023
            int r = idx >> 3;
            int c = (idx & 7) * 4;
            float4 v = *(const float4*)(A + (size_t)(row0 + r) * EMB + kc + c);
            uint4 u = make_uint4(f2tf(v.x), f2tf(v.y), f2tf(v.z), f2tf(v.w));
            *(uint4*)(As + r * 36 + c) = u;
        }
        // B tile: 32 x 64
        #pragma unroll
        for (int i = 0; i < 2; i++) {
            int idx = tid + i * 256;          // 0..511
            int r = idx >> 4;
            int c = (idx & 15) * 4;
            float4 v = *(const float4*)(W + (size_t)(kc + r) * DKH + c);
            uint4 u = make_uint4(f2tf(v.x), f2tf(v.y), f2tf(v.z), f2tf(v.w));
            *(uint4*)(Bs + r * 72 + c) = u;
        }
        __syncthreads();

        #pragma unroll
        for (int ks = 0; ks < 4; ks++) {
            unsigned a[2][4];
            #pragma unroll
            for (int i = 0; i < 2; i++) {
                const unsigned* ap = As + (wm * 32 + i * 16 + g) * 36 + ks * 8 + tg;
                a[i][0] = ap[0];
                a[i][1] = ap[8 * 36];
                a[i][2] = ap[4];
                a[i][3] = ap[8 * 36 + 4];
            }
            unsigned bf[4][2];
            #pragma unroll
            for (int j = 0; j < 4; j++) {
                const unsigned* bp = Bs + (ks * 8 + tg) * 72 + wn * 32 + j * 8 + g;
                bf[j][0] = bp[0];
                bf[j][1] = bp[4 * 72];
            }
            #pragma unroll
            for (int i = 0; i < 2; i++)
                #pragma unroll
                for (int j = 0; j < 4; j++)
                    mma8(acc[i][j], a[i][0], a[i][1], a[i][2], a[i][3],
                         bf[j][0], bf[j][1]);
        }
        __syncthreads();
    }

    // epilogue: bias + scale, vectorized float2 stores
    #pragma unroll
    for (int i = 0; i < 2; i++) {
        int r = row0 + wm * 32 + i * 16 + g;
        #pragma unroll
        for (int j = 0; j < 4; j++) {
            int c = wn * 32 + j * 8 + 2 * tg;
            float b0 = bias[c], b1 = bias[c + 1];
            float2 v0 = make_float2((acc[i][j][0] + b0) * scale,
                                    (acc[i][j][1] + b1) * scale);
            float2 v1 = make_float2((acc[i][j][2] + b0) * scale,
                                    (acc[i][j][3] + b1) * scale);
            *(float2*)(out + (size_t)r * DKH + c)       = v0;
            *(float2*)(out + (size_t)(r + 8) * DKH + c) = v1;
        }
    }
}

// ============================================================================
// Kernel 2: flash attention.  grid = (S/128, B), 256 threads (8 warps x 16 rows).
// Online softmax in registers; P routed through per-warp smem for the PV mma.
// Strides chosen per-array so every frag LDS hits 32 distinct banks.
// ============================================================================
#define KS_STRIDE 68
#define VS_STRIDE 72
#define PS_STRIDE 68
#define SMEM_ATTN ((64*KS_STRIDE + 64*VS_STRIDE + 8*16*PS_STRIDE) * 4)

__global__ __launch_bounds__(256) void attn_kernel(float* __restrict__ out)
{
    extern __shared__ unsigned smem[];
    unsigned* Ks = smem;                       // [64][KS_STRIDE] tf32
    unsigned* Vs = Ks + 64 * KS_STRIDE;        // [64][VS_STRIDE] tf32
    unsigned* Ps = Vs + 64 * VS_STRIDE;        // [8 warps][16][PS_STRIDE] tf32

    const int tid = threadIdx.x;
    const int lane = tid & 31;
    const int wid  = tid >> 5;
    const int g  = lane >> 2;
    const int tg = lane & 3;
    const int b = blockIdx.y;

    const float* Qg = g_Q + ((size_t)b * SL + blockIdx.x * 128 + wid * 16) * DKH;
    const float* Kg = g_K + (size_t)b * SL * DKH;
    const float* Vg = g_V + (size_t)b * SL * DKH;

    // Q fragments (scale already folded in by proj kernel)
    unsigned qa[8][4];
    #pragma unroll
    for (int kt = 0; kt < 8; kt++) {
        const float* q0 = Qg + (size_t)g * DKH + kt * 8 + tg;
        const float* q1 = q0 + 8 * DKH;
        qa[kt][0] = f2tf(q0[0]);
        qa[kt][1] = f2tf(q1[0]);
        qa[kt][2] = f2tf(q0[4]);
        qa[kt][3] = f2tf(q1[4]);
    }

    float o[8][4];
    #pragma unroll
    for (int dt = 0; dt < 8; dt++)
        #pragma unroll
        for (int e = 0; e < 4; e++) o[dt][e] = 0.f;

    float m0 = -3.402823466e38f, m1 = -3.402823466e38f;
    float l0 = 0.f, l1 = 0.f;
    unsigned* Pw = Ps + wid * 16 * PS_STRIDE;

    for (int k0 = 0; k0 < SL; k0 += 64) {
        // load K, V tiles (tf32 converted once at store)
        #pragma unroll
        for (int i = 0; i < 4; i++) {
            int idx = tid + i * 256;         // 0..1023
            int r = idx >> 4;
            int c = (idx & 15) * 4;
            float4 kv = *(const float4*)(Kg + (size_t)(k0 + r) * DKH + c);
            *(uint4*)(Ks + r * KS_STRIDE + c) =
                make_uint4(f2tf(kv.x), f2tf(kv.y), f2tf(kv.z), f2tf(kv.w));
            float4 vv = *(const float4*)(Vg + (size_t)(k0 + r) * DKH + c);
            *(uint4*)(Vs + r * VS_STRIDE + c) =
                make_uint4(f2tf(vv.x), f2tf(vv.y), f2tf(vv.z), f2tf(vv.w));
        }
        __syncthreads();

        // S = Q @ K^T  (16 rows x 64 keys per warp)
        float s[8][4];
        #pragma unroll
        for (int nt = 0; nt < 8; nt++) {
            s[nt][0] = s[nt][1] = s[nt][2] = s[nt][3] = 0.f;
            #pragma unroll
            for (int dk = 0; dk < 8; dk++) {
                const unsigned* kb = Ks + (nt * 8 + g) * KS_STRIDE + dk * 8 + tg;
                mma8(s[nt], qa[dk][0], qa[dk][1], qa[dk][2], qa[dk][3],
                     kb[0], kb[4]);
            }
        }

        // online softmax (rows g and g+8; quad shuffles across tg)
        float mx0 = m0, mx1 = m1;
        #pragma unroll
        for (int nt = 0; nt < 8; nt++) {
            mx0 = fmaxf(mx0, fmaxf(s[nt][0], s[nt][1]));
            mx1 = fmaxf(mx1, fmaxf(s[nt][2], s[nt][3]));
        }
        mx0 = fmaxf(mx0, __shfl_xor_sync(0xffffffffu, mx0, 1));
        mx0 = fmaxf(mx0, __shfl_xor_sync(0xffffffffu, mx0, 2));
        mx1 = fmaxf(mx1, __shfl_xor_sync(0xffffffffu, mx1, 1));
        mx1 = fmaxf(mx1, __shfl_xor_sync(0xffffffffu, mx1, 2));

        float f0 = __expf(m0 - mx0);
        float f1 = __expf(m1 - mx1);

        float sum0 = 0.f, sum1 = 0.f;
        #pragma unroll
        for (int nt = 0; nt < 8; nt++) {
            s[nt][0] = __expf(s[nt][0] - mx0);
            s[nt][1] = __expf(s[nt][1] - mx0);
            s[nt][2] = __expf(s[nt][2] - mx1);
            s[nt][3] = __expf(s[nt][3] - mx1);
            sum0 += s[nt][0] + s[nt][1];
            sum1 += s[nt][2] + s[nt][3];
        }
        sum0 += __shfl_xor_sync(0xffffffffu, sum0, 1);
        sum0 += __shfl_xor_sync(0xffffffffu, sum0, 2);
        sum1 += __shfl_xor_sync(0xffffffffu, sum1, 1);
        sum1 += __shfl_xor_sync(0xffffffffu, sum1, 2);

        l0 = l0 * f0 + sum0;
        l1 = l1 * f1 + sum1;
        m0 = mx0;
        m1 = mx1;

        #pragma unroll
        for (int dt = 0; dt < 8; dt++) {
            o[dt][0] *= f0; o[dt][1] *= f0;
            o[dt][2] *= f1; o[dt][3] *= f1;
        }

        // P -> per-warp smem (tf32)
        #pragma unroll
        for (int nt = 0; nt < 8; nt++) {
            unsigned* p0 = Pw + g * PS_STRIDE + nt * 8 + 2 * tg;
            p0[0] = f2tf(s[nt][0]);
            p0[1] = f2tf(s[nt][1]);
            unsigned* p1 = Pw + (g + 8) * PS_STRIDE + nt * 8 + 2 * tg;
            p1[0] = f2tf(s[nt][2]);
            p1[1] = f2tf(s[nt][3]);
        }
        __syncwarp();

        // O += P @ V
        #pragma unroll
        for (int kk = 0; kk < 8; kk++) {
            const unsigned* pp = Pw + g * PS_STRIDE + kk * 8 + tg;
            const unsigned* pq = Pw + (g + 8) * PS_STRIDE + kk * 8 + tg;
            unsigned pa0 = pp[0], pa2 = pp[4];
            unsigned pa1 = pq[0], pa3 = pq[4];
            #pragma unroll
            for (int dt = 0; dt < 8; dt++) {
                const unsigned* vb = Vs + (kk * 8 + tg) * VS_STRIDE + dt * 8 + g;
                mma8(o[dt], pa0, pa1, pa2, pa3, vb[0], vb[4 * VS_STRIDE]);
            }
        }
        __syncthreads();
    }

    // epilogue: divide by l, store
    float inv0 = 1.f / l0, inv1 = 1.f / l1;
    float* og = out + ((size_t)b * SL + blockIdx.x * 128 + wid * 16) * DKH;
    #pragma unroll
    for (int dt = 0; dt < 8; dt++) {
        int c = dt * 8 + 2 * tg;
        float2 v0 = make_float2(o[dt][0] * inv0, o[dt][1] * inv0);
        float2 v1 = make_float2(o[dt][2] * inv1, o[dt][3] * inv1);
        *(float2*)(og + (size_t)g * DKH + c)       = v0;
        *(float2*)(og + (size_t)(g + 8) * DKH + c) = v1;
    }
}

// ============================================================================
extern "C" void kernel_launch(void* const* d_in, const int* in_sizes, int n_in,
                              void* d_out, int out_size)
{
    const float* in1 = (const float*)d_in[0];
    const float* in2 = (const float*)d_in[1];
    const float* Wq  = (const float*)d_in[2];
    const float* bq  = (const float*)d_in[3];
    const float* Wk  = (const float*)d_in[4];
    const float* bk  = (const float*)d_in[5];
    const float* Wv  = (const float*)d_in[6];
    const float* bv  = (const float*)d_in[7];
    float* out = (float*)d_out;

    // attribute set is idempotent and not a stream op (capture-safe)
    cudaFuncSetAttribute(attn_kernel,
                         cudaFuncAttributeMaxDynamicSharedMemorySize, SMEM_ATTN);

    proj_kernel<<<dim3(MTOT / 128, 3), 256>>>(in1, in2, Wq, bq, Wk, bk, Wv, bv);
    attn_kernel<<<dim3(SL / 128, NB), 256, SMEM_ATTN>>>(out);
}